// round 8
// baseline (speedup 1.0000x reference)
#include <cuda_runtime.h>
#include <cuda_bf16.h>
#include <math.h>
#include <stdint.h>

// ---------------------------------------------------------------------------
// Problem constants
// ---------------------------------------------------------------------------
#define BB        16
#define TT        8
#define NB        4
#define C_INC     2048       // C_IN
#define C_INR     512        // C_INNER
#define WW        14
#define HWP       196        // H*W
#define M_TOTAL   25088      // FRAMES*HW
#define K_FEATS   4608       // C_INNER*9
#define NROIS     512
#define NCLS      174
#define NOBJ      301

#define OUT_OBJCLS_OFF 2784
#define OUT_LABEL_OFF  12416

// ---------------------------------------------------------------------------
// Scratch
// ---------------------------------------------------------------------------
__device__ float g_fm[M_TOTAL * C_INR];        // [frame][hw][o]
__device__ float g_wtf[C_INR * C_INC];         // conv5_w tf32(RN), [n][k]
__device__ float g_rewt[C_INR * K_FEATS];      // re_w^T tf32, [n][k'], k'=c*9+bin
__device__ float g_feats[NROIS * K_FEATS];     // [roi][k'], tf32-rounded
__device__ float g_regacc[NROIS * C_INR];
__device__ float g_pooled[BB * C_INR];
__device__ float g_objfeas[2 * BB * C_INR];

// ---------------------------------------------------------------------------
// Helpers
// ---------------------------------------------------------------------------
__device__ __forceinline__ uint32_t smem_u32(const void* p) {
    uint32_t a;
    asm("{ .reg .u64 t; cvta.to.shared.u64 t, %1; cvt.u32.u64 %0, t; }"
        : "=r"(a) : "l"(p));
    return a;
}
__device__ __forceinline__ uint32_t f2tf32(float v) {
    uint32_t o;
    asm("cvt.rna.tf32.f32 %0, %1;" : "=r"(o) : "f"(v));
    return o;
}
#define LDS32(v, a) asm volatile("ld.shared.b32 %0, [%1];" : "=r"(v) : "r"(a))

__device__ __forceinline__ void mma_tf32(float& d0, float& d1, float& d2, float& d3,
                                         uint32_t a0, uint32_t a1, uint32_t a2, uint32_t a3,
                                         uint32_t b0, uint32_t b1)
{
    asm volatile(
        "mma.sync.aligned.m16n8k8.row.col.f32.tf32.tf32.f32 "
        "{%0,%1,%2,%3}, {%4,%5,%6,%7}, {%8,%9}, {%0,%1,%2,%3};"
        : "+f"(d0), "+f"(d1), "+f"(d2), "+f"(d3)
        : "r"(a0), "r"(a1), "r"(a2), "r"(a3), "r"(b0), "r"(b1));
}

// ---------------------------------------------------------------------------
// Weight pre-passes
// ---------------------------------------------------------------------------
__global__ void wconv_kernel(const float* __restrict__ w)
{
    int i = blockIdx.x * blockDim.x + threadIdx.x;
    if (i < C_INR * C_INC)
        g_wtf[i] = __uint_as_float(f2tf32(w[i]));
}

__global__ void rewt_kernel(const float* __restrict__ rw)
{
    __shared__ float t[32][33];
    const int r0 = blockIdx.x * 32;
    const int c0 = blockIdx.y * 32;
    const int cx = threadIdx.x;
    const int ty = threadIdx.y;
#pragma unroll
    for (int j = 0; j < 4; ++j) {
        int ry = ty + j * 8;
        t[ry][cx] = rw[(size_t)(r0 + ry) * C_INR + c0 + cx];
    }
    __syncthreads();
#pragma unroll
    for (int j = 0; j < 4; ++j) {
        int ry = ty + j * 8;
        g_rewt[(size_t)(c0 + ry) * K_FEATS + r0 + cx] =
            __uint_as_float(f2tf32(t[cx][ry]));
    }
}

// ---------------------------------------------------------------------------
// GEMM1: CTA 128x128, BK=32, 4 warps (2x2), warp 64x64, 3 CTAs/SM target.
// ---------------------------------------------------------------------------
#define G1_ITERS   (C_INC / 32)     // 64
#define G1_SMEM    65536

__global__ void __launch_bounds__(128, 3) gemm1_mma(const float* __restrict__ x)
{
    extern __shared__ char sm[];
    const uint32_t sbase = smem_u32(sm);
    const int tid  = threadIdx.x;
    const int wid  = tid >> 5;
    const int lane = tid & 31;
    const int n0   = blockIdx.x * 128;
    const int m0   = blockIdx.y * 128;

    // A loader: one m per thread
    const float* xb;
    {
        int mm = m0 + tid;
        int frame = mm / HWP;
        int hw = mm - frame * HWP;
        int b = frame >> 3, t = frame & 7;
        xb = x + (size_t)b * (C_INC * TT * HWP) + (size_t)t * HWP + hw;
    }
    const uint32_t a_row = (uint32_t)tid * 128;
    const uint32_t a_sw  = ((uint32_t)tid & 7) << 4;

    const int wm = (wid >> 1) * 64;
    const int wn = (wid & 1) * 64;
    const int g  = lane >> 2;
    const int tg = lane & 3;
    const uint32_t frag_sw = ((uint32_t)g & 7) << 4;
    const uint32_t aoff0 = (uint32_t)(wm + g) * 128;
    const uint32_t boff0 = (uint32_t)(wn + g) * 128 + 32768u;

    float acc[4][8][4];
#pragma unroll
    for (int i = 0; i < 4; i++)
#pragma unroll
        for (int j = 0; j < 8; j++)
#pragma unroll
            for (int r = 0; r < 4; r++) acc[i][j][r] = 0.0f;

    // ---------------- prologue: stage s=0 into buf 0
#pragma unroll
    for (int kc = 0; kc < 4; ++kc) {
        float ar[8];
#pragma unroll
        for (int j = 0; j < 8; ++j)
            ar[j] = xb[(size_t)(kc * 8 + j) * (TT * HWP)];
        uint32_t d0 = sbase + a_row + (((uint32_t)(kc * 32))      ^ a_sw);
        uint32_t d1 = sbase + a_row + (((uint32_t)(kc * 32 + 16)) ^ a_sw);
        asm volatile("st.shared.v4.b32 [%0], {%1,%2,%3,%4};" :: "r"(d0),
            "r"(f2tf32(ar[0])), "r"(f2tf32(ar[1])), "r"(f2tf32(ar[2])), "r"(f2tf32(ar[3])));
        asm volatile("st.shared.v4.b32 [%0], {%1,%2,%3,%4};" :: "r"(d1),
            "r"(f2tf32(ar[4])), "r"(f2tf32(ar[5])), "r"(f2tf32(ar[6])), "r"(f2tf32(ar[7])));
    }
#pragma unroll
    for (int i = 0; i < 8; ++i) {
        int idx = tid + i * 128;
        int n = idx >> 3, c = idx & 7;
        const float* src = g_wtf + (size_t)(n0 + n) * C_INC + c * 4;
        uint32_t dst = sbase + 32768u + (uint32_t)n * 128
                     + (((uint32_t)c * 16) ^ (((uint32_t)n & 7) << 4));
        asm volatile("cp.async.cg.shared.global [%0], [%1], 16;" :: "r"(dst), "l"(src));
    }
    asm volatile("cp.async.commit_group;" ::: "memory");

    // ---------------- main loop
    for (int s = 0; s < G1_ITERS; ++s) {
        const uint32_t bufo = (s & 1) ? 16384u : 0u;
        const uint32_t nbuf = (s & 1) ? 0u : 16384u;

        asm volatile("cp.async.wait_group 0;" ::: "memory");
        __syncthreads();

        const bool pf = (s + 1 < G1_ITERS);
        const float* xn = xb + (size_t)(s + 1) * 32 * (TT * HWP);

        if (pf) {
            const int k0n = (s + 1) * 32;
#pragma unroll
            for (int i = 0; i < 8; ++i) {
                int idx = tid + i * 128;
                int n = idx >> 3, c = idx & 7;
                const float* src = g_wtf + (size_t)(n0 + n) * C_INC + k0n + c * 4;
                uint32_t dst = sbase + 32768u + nbuf + (uint32_t)n * 128
                             + (((uint32_t)c * 16) ^ (((uint32_t)n & 7) << 4));
                asm volatile("cp.async.cg.shared.global [%0], [%1], 16;" :: "r"(dst), "l"(src));
            }
            asm volatile("cp.async.commit_group;" ::: "memory");
        }

        const uint32_t Ab = sbase + bufo;
        const uint32_t Bb = sbase + bufo;   // boff0 carries +32768

#pragma unroll
        for (int kc = 0; kc < 4; ++kc) {
            // A prefetch phase kc (for iter s+1): 8 LDGs, latency hides under MMAs
            float ar[8];
            if (pf) {
#pragma unroll
                for (int j = 0; j < 8; ++j)
                    ar[j] = xn[(size_t)(kc * 8 + j) * (TT * HWP)];
            }

            const uint32_t u0 = (uint32_t)(kc * 32 + tg * 4)      ^ frag_sw;
            const uint32_t u1 = (uint32_t)(kc * 32 + tg * 4 + 16) ^ frag_sw;

            uint32_t af[4][4];
#pragma unroll
            for (int mt = 0; mt < 4; ++mt) {
                uint32_t base = Ab + aoff0 + (uint32_t)mt * 2048;
                LDS32(af[mt][0], base + u0);
                LDS32(af[mt][1], base + 1024 + u0);
                LDS32(af[mt][2], base + u1);
                LDS32(af[mt][3], base + 1024 + u1);
            }
#pragma unroll
            for (int nt = 0; nt < 8; ++nt) {
                uint32_t b0, b1;
                uint32_t base = Bb + boff0 + (uint32_t)nt * 1024;
                LDS32(b0, base + u0);
                LDS32(b1, base + u1);
#pragma unroll
                for (int mt = 0; mt < 4; ++mt)
                    mma_tf32(acc[mt][nt][0], acc[mt][nt][1], acc[mt][nt][2], acc[mt][nt][3],
                             af[mt][0], af[mt][1], af[mt][2], af[mt][3], b0, b1);
            }

            if (pf) {
                uint32_t d0 = sbase + nbuf + a_row + (((uint32_t)(kc * 32))      ^ a_sw);
                uint32_t d1 = sbase + nbuf + a_row + (((uint32_t)(kc * 32 + 16)) ^ a_sw);
                asm volatile("st.shared.v4.b32 [%0], {%1,%2,%3,%4};" :: "r"(d0),
                    "r"(f2tf32(ar[0])), "r"(f2tf32(ar[1])), "r"(f2tf32(ar[2])), "r"(f2tf32(ar[3])));
                asm volatile("st.shared.v4.b32 [%0], {%1,%2,%3,%4};" :: "r"(d1),
                    "r"(f2tf32(ar[4])), "r"(f2tf32(ar[5])), "r"(f2tf32(ar[6])), "r"(f2tf32(ar[7])));
            }
        }
    }

    // ---------------- epilogue
#pragma unroll
    for (int mt = 0; mt < 4; ++mt) {
#pragma unroll
        for (int nt = 0; nt < 8; ++nt) {
            int gm = m0 + wm + mt * 16 + g;
            int gn = n0 + wn + nt * 8 + tg * 2;
            float2 v0 = make_float2(acc[mt][nt][0], acc[mt][nt][1]);
            float2 v1 = make_float2(acc[mt][nt][2], acc[mt][nt][3]);
            *(float2*)&g_fm[(size_t)gm * C_INR + gn]       = v0;
            *(float2*)&g_fm[(size_t)(gm + 8) * C_INR + gn] = v1;
        }
    }
}

// ---------------------------------------------------------------------------
// ROI align: 2 blocks per ROI (64 channels-groups each), 64 threads
// ---------------------------------------------------------------------------
__global__ __launch_bounds__(64)
void roi_kernel(const float* __restrict__ boxes)
{
    const int r     = blockIdx.x >> 1;
    const int c4    = ((blockIdx.x & 1) << 6) + threadIdx.x;   // 0..127
    const int frame = r >> 2;

    const float* bx = boxes + r * 4;
    float cx = bx[0], cy = bx[1], w = bx[2], h = bx[3];

    float x1 = ((cx - w * 0.5f) * 224.0f) * 0.0625f;
    float y1 = ((cy - h * 0.5f) * 224.0f) * 0.0625f;
    float x2 = ((cx + w * 0.5f) * 224.0f) * 0.0625f;
    float y2 = ((cy + h * 0.5f) * 224.0f) * 0.0625f;

    float roi_w = fmaxf(x2 - x1, 1.0f);
    float roi_h = fmaxf(y2 - y1, 1.0f);
    float bw = roi_w * (1.0f / 3.0f);
    float bh = roi_h * (1.0f / 3.0f);

    float4 acc[9];
#pragma unroll
    for (int i = 0; i < 9; i++) acc[i] = make_float4(0.f, 0.f, 0.f, 0.f);

    const float* fmf = g_fm + (size_t)frame * HWP * C_INR + c4 * 4;

#pragma unroll
    for (int iy = 0; iy < 6; iy++) {
        float yy = y1 + (float)(iy >> 1) * bh + ((float)(iy & 1) + 0.5f) * bh * 0.5f;
        bool vy = (yy > -1.0f) && (yy < 14.0f);
        float yc = fminf(fmaxf(yy, 0.0f), 13.0f);
        int   yi0 = (int)floorf(yc);
        int   yi1 = min(yi0 + 1, 13);
        float ly = yc - (float)yi0;
        float hy = 1.0f - ly;

#pragma unroll
        for (int ix = 0; ix < 6; ix++) {
            float xx = x1 + (float)(ix >> 1) * bw + ((float)(ix & 1) + 0.5f) * bw * 0.5f;
            bool v = vy && (xx > -1.0f) && (xx < 14.0f);
            if (!v) continue;
            float xc = fminf(fmaxf(xx, 0.0f), 13.0f);
            int   xi0 = (int)floorf(xc);
            int   xi1 = min(xi0 + 1, 13);
            float lx = xc - (float)xi0;
            float hx = 1.0f - lx;

            float w00 = hy * hx, w01 = hy * lx, w10 = ly * hx, w11 = ly * lx;

            float4 p00 = *(const float4*)(fmf + (yi0 * WW + xi0) * C_INR);
            float4 p01 = *(const float4*)(fmf + (yi0 * WW + xi1) * C_INR);
            float4 p10 = *(const float4*)(fmf + (yi1 * WW + xi0) * C_INR);
            float4 p11 = *(const float4*)(fmf + (yi1 * WW + xi1) * C_INR);

            int bin = (iy >> 1) * 3 + (ix >> 1);
            acc[bin].x += w00 * p00.x + w01 * p01.x + w10 * p10.x + w11 * p11.x;
            acc[bin].y += w00 * p00.y + w01 * p01.y + w10 * p10.y + w11 * p11.y;
            acc[bin].z += w00 * p00.z + w01 * p01.z + w10 * p10.z + w11 * p11.z;
            acc[bin].w += w00 * p00.w + w01 * p01.w + w10 * p10.w + w11 * p11.w;
        }
    }

    float tmp[36];
#pragma unroll
    for (int bin = 0; bin < 9; bin++) {
        tmp[0 * 9 + bin] = __uint_as_float(f2tf32(acc[bin].x * 0.25f));
        tmp[1 * 9 + bin] = __uint_as_float(f2tf32(acc[bin].y * 0.25f));
        tmp[2 * 9 + bin] = __uint_as_float(f2tf32(acc[bin].z * 0.25f));
        tmp[3 * 9 + bin] = __uint_as_float(f2tf32(acc[bin].w * 0.25f));
    }
    float* out = g_feats + (size_t)r * K_FEATS + c4 * 36;
#pragma unroll
    for (int q = 0; q < 9; q++)
        *(float4*)(out + q * 4) = *(float4*)&tmp[q * 4];
}

// ---------------------------------------------------------------------------
__global__ void zero_kernel()
{
    int i = blockIdx.x * blockDim.x + threadIdx.x;
    if (i < NROIS * C_INR) g_regacc[i] = 0.0f;
}

// ---------------------------------------------------------------------------
// GEMM2 via mma.sync tf32, split-K=8
// ---------------------------------------------------------------------------
#define G2_SPLITS 8
#define G2_KC     (K_FEATS / G2_SPLITS)   // 576
#define G2_ITERS  (G2_KC / 32)            // 18
#define G2_SMEM   65536

__global__ void __launch_bounds__(256, 2) gemm2_mma()
{
    extern __shared__ char sm[];
    const uint32_t sbase = smem_u32(sm);
    const int tid  = threadIdx.x;
    const int wid  = tid >> 5;
    const int lane = tid & 31;
    const int m0   = blockIdx.x * 128;
    const int n0   = blockIdx.y * 128;
    const int kb   = blockIdx.z * G2_KC;

    const int wm = (wid >> 2) * 64;
    const int wn = (wid & 3) * 32;
    const int g  = lane >> 2;
    const int tg = lane & 3;
    const uint32_t frag_sw = ((uint32_t)g & 7) << 4;
    const uint32_t aoff0 = (uint32_t)(wm + g) * 128;
    const uint32_t boff0 = (uint32_t)(wn + g) * 128 + 32768u;

    float acc[4][4][4];
#pragma unroll
    for (int i = 0; i < 4; i++)
#pragma unroll
        for (int j = 0; j < 4; j++)
#pragma unroll
            for (int r = 0; r < 4; r++) acc[i][j][r] = 0.0f;

#pragma unroll
    for (int i = 0; i < 4; ++i) {
        int idx = tid + i * 256;
        int rr = idx >> 3, c = idx & 7;
        uint32_t sw = (((uint32_t)c * 16) ^ (((uint32_t)rr & 7) << 4));
        const float* asrc = g_feats + (size_t)(m0 + rr) * K_FEATS + kb + c * 4;
        const float* bsrc = g_rewt  + (size_t)(n0 + rr) * K_FEATS + kb + c * 4;
        uint32_t adst = sbase + (uint32_t)rr * 128 + sw;
        uint32_t bdst = sbase + 32768u + (uint32_t)rr * 128 + sw;
        asm volatile("cp.async.cg.shared.global [%0], [%1], 16;" :: "r"(adst), "l"(asrc));
        asm volatile("cp.async.cg.shared.global [%0], [%1], 16;" :: "r"(bdst), "l"(bsrc));
    }
    asm volatile("cp.async.commit_group;" ::: "memory");

    for (int s = 0; s < G2_ITERS; ++s) {
        const uint32_t bufo = (s & 1) ? 16384u : 0u;

        asm volatile("cp.async.wait_group 0;" ::: "memory");
        __syncthreads();

        if (s + 1 < G2_ITERS) {
            const int k0n = kb + (s + 1) * 32;
            const uint32_t nb = (s + 1) & 1 ? 16384u : 0u;
#pragma unroll
            for (int i = 0; i < 4; ++i) {
                int idx = tid + i * 256;
                int rr = idx >> 3, c = idx & 7;
                uint32_t sw = (((uint32_t)c * 16) ^ (((uint32_t)rr & 7) << 4));
                const float* asrc = g_feats + (size_t)(m0 + rr) * K_FEATS + k0n + c * 4;
                const float* bsrc = g_rewt  + (size_t)(n0 + rr) * K_FEATS + k0n + c * 4;
                uint32_t adst = sbase + nb + (uint32_t)rr * 128 + sw;
                uint32_t bdst = sbase + 32768u + nb + (uint32_t)rr * 128 + sw;
                asm volatile("cp.async.cg.shared.global [%0], [%1], 16;" :: "r"(adst), "l"(asrc));
                asm volatile("cp.async.cg.shared.global [%0], [%1], 16;" :: "r"(bdst), "l"(bsrc));
            }
            asm volatile("cp.async.commit_group;" ::: "memory");
        }

        const uint32_t Ab = sbase + bufo;
        const uint32_t Bb = sbase + bufo;
#pragma unroll
        for (int kc = 0; kc < 4; ++kc) {
            const uint32_t u0 = (uint32_t)(kc * 32 + tg * 4)      ^ frag_sw;
            const uint32_t u1 = (uint32_t)(kc * 32 + tg * 4 + 16) ^ frag_sw;

            uint32_t af[4][4];
#pragma unroll
            for (int mt = 0; mt < 4; ++mt) {
                uint32_t base = Ab + aoff0 + (uint32_t)mt * 2048;
                LDS32(af[mt][0], base + u0);
                LDS32(af[mt][1], base + 1024 + u0);
                LDS32(af[mt][2], base + u1);
                LDS32(af[mt][3], base + 1024 + u1);
            }
#pragma unroll
            for (int nt = 0; nt < 4; ++nt) {
                uint32_t b0, b1;
                uint32_t base = Bb + boff0 + (uint32_t)nt * 1024;
                LDS32(b0, base + u0);
                LDS32(b1, base + u1);
#pragma unroll
                for (int mt = 0; mt < 4; ++mt)
                    mma_tf32(acc[mt][nt][0], acc[mt][nt][1], acc[mt][nt][2], acc[mt][nt][3],
                             af[mt][0], af[mt][1], af[mt][2], af[mt][3], b0, b1);
            }
        }
    }

#pragma unroll
    for (int mt = 0; mt < 4; ++mt) {
#pragma unroll
        for (int nt = 0; nt < 4; ++nt) {
            int gm = m0 + wm + mt * 16 + g;
            int gn = n0 + wn + nt * 8 + tg * 2;
            atomicAdd(&g_regacc[(size_t)gm * C_INR + gn],           acc[mt][nt][0]);
            atomicAdd(&g_regacc[(size_t)gm * C_INR + gn + 1],       acc[mt][nt][1]);
            atomicAdd(&g_regacc[(size_t)(gm + 8) * C_INR + gn],     acc[mt][nt][2]);
            atomicAdd(&g_regacc[(size_t)(gm + 8) * C_INR + gn + 1], acc[mt][nt][3]);
        }
    }
}

// ---------------------------------------------------------------------------
__global__ __launch_bounds__(512)
void reduce_kernel(const float* __restrict__ re_b, const int* __restrict__ cat,
                   float* __restrict__ out, int out_size)
{
    const int b = blockIdx.x;
    const int j = threadIdx.x;
    const float bias = re_b[j];

    float rm[NB];
    float p = 0.0f;
#pragma unroll
    for (int nb = 0; nb < NB; nb++) {
        float s = 0.0f;
#pragma unroll
        for (int t = 0; t < TT; t++) {
            int r = (b * TT + t) * NB + nb;
            s += fmaxf(g_regacc[(size_t)r * C_INR + j] + bias, 0.0f);
        }
        rm[nb] = s * 0.125f;
        p += rm[nb];
    }
    g_pooled[b * C_INR + j] = p * 0.25f;

    int c2 = cat[b * NB + 2];
    int c3 = cat[b * NB + 3];
    int o0 = (c2 == 0 && c3 != 0) ? 1 : 0;
    int o1 = 1 - o0;
    g_objfeas[(2 * b) * C_INR + j]     = rm[2 + o0];
    g_objfeas[(2 * b + 1) * C_INR + j] = rm[2 + o1];

    if (j == 0 && out_size >= OUT_LABEL_OFF + 2 * BB) {
        out[OUT_LABEL_OFF + 2 * b]     = (float)(o0 == 0 ? c2 : c3);
        out[OUT_LABEL_OFF + 2 * b + 1] = (float)(o1 == 0 ? c2 : c3);
    }
}

// ---------------------------------------------------------------------------
// Fused two-layer head: out[m] = (X[m] @ W1 + b1) @ W2 + b2   (K=512 both)
// ---------------------------------------------------------------------------
__global__ __launch_bounds__(256)
void head2_kernel(const float* __restrict__ X,
                  const float* __restrict__ W1, const float* __restrict__ b1,
                  const float* __restrict__ W2, const float* __restrict__ b2,
                  float* __restrict__ out, int N2)
{
    __shared__ float xs[512];
    __shared__ float hid[512];
    const int m = blockIdx.x;
    for (int k = threadIdx.x; k < 512; k += 256) xs[k] = X[m * 512 + k];
    __syncthreads();

#pragma unroll
    for (int rr = 0; rr < 2; ++rr) {
        int n = threadIdx.x + rr * 256;
        float a = b1[n];
#pragma unroll 8
        for (int k = 0; k < 512; ++k)
            a = fmaf(xs[k], __ldg(&W1[(size_t)k * 512 + n]), a);
        hid[n] = a;
    }
    __syncthreads();

    for (int n = threadIdx.x; n < N2; n += 256) {
        float a = b2[n];
#pragma unroll 8
        for (int k = 0; k < 512; ++k)
            a = fmaf(hid[k], __ldg(&W2[(size_t)k * N2 + n]), a);
        out[m * N2 + n] = a;
    }
}

// ---------------------------------------------------------------------------
// kernel_launch
// ---------------------------------------------------------------------------
extern "C" void kernel_launch(void* const* d_in, const int* in_sizes, int n_in,
                              void* d_out, int out_size)
{
    const float* x       = (const float*)d_in[0];
    const float* boxes   = (const float*)d_in[1];
    const int*   cat     = (const int*)  d_in[2];
    const float* conv5_w = (const float*)d_in[3];
    const float* re_w    = (const float*)d_in[4];
    const float* re_b    = (const float*)d_in[5];
    const float* oc1_w   = (const float*)d_in[6];
    const float* oc1_b   = (const float*)d_in[7];
    const float* oc2_w   = (const float*)d_in[8];
    const float* oc2_b   = (const float*)d_in[9];
    const float* pr1_w   = (const float*)d_in[10];
    const float* pr1_b   = (const float*)d_in[11];
    const float* pr2_w   = (const float*)d_in[12];
    const float* pr2_b   = (const float*)d_in[13];
    float* out = (float*)d_out;

    float *p_pooled, *p_objfeas;
    cudaGetSymbolAddress((void**)&p_pooled,  g_pooled);
    cudaGetSymbolAddress((void**)&p_objfeas, g_objfeas);

    cudaFuncSetAttribute(gemm1_mma, cudaFuncAttributeMaxDynamicSharedMemorySize, G1_SMEM);
    cudaFuncSetAttribute(gemm2_mma, cudaFuncAttributeMaxDynamicSharedMemorySize, G2_SMEM);

    // 0) weight pre-passes + zero
    wconv_kernel<<<(C_INR * C_INC + 511) / 512, 512>>>(conv5_w);
    rewt_kernel<<<dim3(K_FEATS / 32, C_INR / 32), dim3(32, 8)>>>(re_w);
    zero_kernel<<<(NROIS * C_INR + 255) / 256, 256>>>();

    // 1) big 1x1-conv GEMM (tf32 mma, 64x64 warp tiles, 3 CTAs/SM)
    gemm1_mma<<<dim3(C_INR / 128, M_TOTAL / 128), 128, G1_SMEM>>>(x);

    // 2) ROI align (2 blocks/ROI)
    roi_kernel<<<NROIS * 2, 64>>>(boxes);

    // 3) feats @ re_w, split-K=8 + atomics
    gemm2_mma<<<dim3(4, 4, G2_SPLITS), 256, G2_SMEM>>>();

    // 4) bias+relu+T-mean, NB-mean pool, obj selection + labels
    reduce_kernel<<<BB, 512>>>(re_b, cat, out, out_size);

    // 5) fused heads
    head2_kernel<<<2 * BB, 256>>>(p_objfeas, oc1_w, oc1_b, oc2_w, oc2_b,
                                  out + OUT_OBJCLS_OFF, NOBJ);
    head2_kernel<<<BB, 256>>>(p_pooled, pr1_w, pr1_b, pr2_w, pr2_b, out, NCLS);
}

// round 9
// speedup vs baseline: 1.5097x; 1.5097x over previous
#include <cuda_runtime.h>
#include <cuda_bf16.h>
#include <math.h>
#include <stdint.h>

// ---------------------------------------------------------------------------
// Problem constants
// ---------------------------------------------------------------------------
#define BB        16
#define TT        8
#define NB        4
#define C_INC     2048       // C_IN
#define C_INR     512        // C_INNER
#define WW        14
#define HWP       196        // H*W
#define MLOC      1568       // T*H*W per batch
#define M_TOTAL   25088      // FRAMES*HW
#define K_FEATS   4608       // C_INNER*9
#define NROIS     512
#define NCLS      174
#define NOBJ      301

#define OUT_OBJCLS_OFF 2784
#define OUT_LABEL_OFF  12416

// ---------------------------------------------------------------------------
// Scratch
// ---------------------------------------------------------------------------
__device__ float g_xt[M_TOTAL * C_INC];        // x transposed, tf32(RN), [m][k]
__device__ float g_fm[M_TOTAL * C_INR];        // [frame][hw][o]
__device__ float g_wtf[C_INR * C_INC];         // conv5_w tf32(RN), [n][k]
__device__ float g_rewt[C_INR * K_FEATS];      // re_w^T tf32, [n][k'], k'=c*9+bin
__device__ float g_feats[NROIS * K_FEATS];     // [roi][k'], tf32-rounded
__device__ float g_regacc[NROIS * C_INR];
__device__ float g_pooled[BB * C_INR];
__device__ float g_objfeas[2 * BB * C_INR];

// ---------------------------------------------------------------------------
// Helpers
// ---------------------------------------------------------------------------
__device__ __forceinline__ uint32_t smem_u32(const void* p) {
    uint32_t a;
    asm("{ .reg .u64 t; cvta.to.shared.u64 t, %1; cvt.u32.u64 %0, t; }"
        : "=r"(a) : "l"(p));
    return a;
}
__device__ __forceinline__ uint32_t f2tf32(float v) {
    uint32_t o;
    asm("cvt.rna.tf32.f32 %0, %1;" : "=r"(o) : "f"(v));
    return o;
}
#define LDS32(v, a) asm volatile("ld.shared.b32 %0, [%1];" : "=r"(v) : "r"(a))

__device__ __forceinline__ void mma_tf32(float& d0, float& d1, float& d2, float& d3,
                                         uint32_t a0, uint32_t a1, uint32_t a2, uint32_t a3,
                                         uint32_t b0, uint32_t b1)
{
    asm volatile(
        "mma.sync.aligned.m16n8k8.row.col.f32.tf32.tf32.f32 "
        "{%0,%1,%2,%3}, {%4,%5,%6,%7}, {%8,%9}, {%0,%1,%2,%3};"
        : "+f"(d0), "+f"(d1), "+f"(d2), "+f"(d3)
        : "r"(a0), "r"(a1), "r"(a2), "r"(a3), "r"(b0), "r"(b1));
}

// ---------------------------------------------------------------------------
// Pre-passes
// ---------------------------------------------------------------------------
__global__ void wconv_kernel(const float* __restrict__ w)
{
    int i = blockIdx.x * blockDim.x + threadIdx.x;
    if (i < C_INR * C_INC)
        g_wtf[i] = __uint_as_float(f2tf32(w[i]));
}

// x[b][k][t][hw] -> g_xt[(b,t,hw)][k], rounded to tf32(RN). Tiled 32x32.
__global__ void xt_kernel(const float* __restrict__ x)
{
    __shared__ float t[32][33];
    const int k0  = blockIdx.x * 32;
    const int ml0 = blockIdx.y * 32;
    const int b   = blockIdx.z;
    const int cx  = threadIdx.x;     // 0..31
    const int ty  = threadIdx.y;     // 0..7

    const float* src = x + (size_t)b * C_INC * MLOC + (size_t)k0 * MLOC + ml0;
#pragma unroll
    for (int j = 0; j < 4; ++j) {
        int ry = ty + j * 8;
        t[ry][cx] = src[(size_t)ry * MLOC + cx];
    }
    __syncthreads();
    float* dst = g_xt + (size_t)(b * MLOC + ml0) * C_INC + k0;
#pragma unroll
    for (int j = 0; j < 4; ++j) {
        int ry = ty + j * 8;
        dst[(size_t)ry * C_INC + cx] = __uint_as_float(f2tf32(t[cx][ry]));
    }
}

__global__ void rewt_kernel(const float* __restrict__ rw)
{
    __shared__ float t[32][33];
    const int r0 = blockIdx.x * 32;
    const int c0 = blockIdx.y * 32;
    const int cx = threadIdx.x;
    const int ty = threadIdx.y;
#pragma unroll
    for (int j = 0; j < 4; ++j) {
        int ry = ty + j * 8;
        t[ry][cx] = rw[(size_t)(r0 + ry) * C_INR + c0 + cx];
    }
    __syncthreads();
#pragma unroll
    for (int j = 0; j < 4; ++j) {
        int ry = ty + j * 8;
        g_rewt[(size_t)(c0 + ry) * K_FEATS + r0 + cx] =
            __uint_as_float(f2tf32(t[cx][ry]));
    }
}

// ---------------------------------------------------------------------------
// GEMM1: fm[m][n] = sum_k xt(m,k) * w(n,k). CTA 128x128, BK=32,
// 4 warps (2x2), warp 64x64. Both operands cp.async. 3 CTAs/SM.
// ---------------------------------------------------------------------------
#define G1_ITERS   (C_INC / 32)     // 64
#define G1_SMEM    65536

__global__ void __launch_bounds__(128, 3) gemm1_mma()
{
    extern __shared__ char sm[];
    const uint32_t sbase = smem_u32(sm);
    const int tid  = threadIdx.x;
    const int wid  = tid >> 5;
    const int lane = tid & 31;
    const int n0   = blockIdx.x * 128;
    const int m0   = blockIdx.y * 128;

    const int wm = (wid >> 1) * 64;
    const int wn = (wid & 1) * 64;
    const int g  = lane >> 2;
    const int tg = lane & 3;
    const uint32_t frag_sw = ((uint32_t)g & 7) << 4;
    const uint32_t aoff0 = (uint32_t)(wm + g) * 128;
    const uint32_t boff0 = (uint32_t)(wn + g) * 128 + 32768u;

    // loader mapping: 8 chunks per tile per thread
    const int lrr = tid >> 3;          // row 0..15 step: +16 per i? no: idx scheme below
    float acc[4][8][4];
#pragma unroll
    for (int i = 0; i < 4; i++)
#pragma unroll
        for (int j = 0; j < 8; j++)
#pragma unroll
            for (int r = 0; r < 4; r++) acc[i][j][r] = 0.0f;

    // ---------------- prologue: stage k0 = 0 into buf 0
#pragma unroll
    for (int i = 0; i < 8; ++i) {
        int idx = tid + i * 128;
        int rr = idx >> 3, c = idx & 7;
        uint32_t sw = (((uint32_t)c * 16) ^ (((uint32_t)rr & 7) << 4));
        const float* asrc = g_xt  + (size_t)(m0 + rr) * C_INC + c * 4;
        const float* bsrc = g_wtf + (size_t)(n0 + rr) * C_INC + c * 4;
        uint32_t adst = sbase + (uint32_t)rr * 128 + sw;
        uint32_t bdst = sbase + 32768u + (uint32_t)rr * 128 + sw;
        asm volatile("cp.async.cg.shared.global [%0], [%1], 16;" :: "r"(adst), "l"(asrc));
        asm volatile("cp.async.cg.shared.global [%0], [%1], 16;" :: "r"(bdst), "l"(bsrc));
    }
    asm volatile("cp.async.commit_group;" ::: "memory");

    // ---------------- main loop
    for (int s = 0; s < G1_ITERS; ++s) {
        const uint32_t bufo = (s & 1) ? 16384u : 0u;
        const uint32_t nbuf = (s & 1) ? 0u : 16384u;

        asm volatile("cp.async.wait_group 0;" ::: "memory");
        __syncthreads();

        if (s + 1 < G1_ITERS) {
            const int k0n = (s + 1) * 32;
#pragma unroll
            for (int i = 0; i < 8; ++i) {
                int idx = tid + i * 128;
                int rr = idx >> 3, c = idx & 7;
                uint32_t sw = (((uint32_t)c * 16) ^ (((uint32_t)rr & 7) << 4));
                const float* asrc = g_xt  + (size_t)(m0 + rr) * C_INC + k0n + c * 4;
                const float* bsrc = g_wtf + (size_t)(n0 + rr) * C_INC + k0n + c * 4;
                uint32_t adst = sbase + nbuf + (uint32_t)rr * 128 + sw;
                uint32_t bdst = sbase + 32768u + nbuf + (uint32_t)rr * 128 + sw;
                asm volatile("cp.async.cg.shared.global [%0], [%1], 16;" :: "r"(adst), "l"(asrc));
                asm volatile("cp.async.cg.shared.global [%0], [%1], 16;" :: "r"(bdst), "l"(bsrc));
            }
            asm volatile("cp.async.commit_group;" ::: "memory");
        }

        const uint32_t Ab = sbase + bufo;
        const uint32_t Bb = sbase + bufo;   // boff0 carries +32768
#pragma unroll
        for (int kc = 0; kc < 4; ++kc) {
            const uint32_t u0 = (uint32_t)(kc * 32 + tg * 4)      ^ frag_sw;
            const uint32_t u1 = (uint32_t)(kc * 32 + tg * 4 + 16) ^ frag_sw;

            uint32_t af[4][4];
#pragma unroll
            for (int mt = 0; mt < 4; ++mt) {
                uint32_t base = Ab + aoff0 + (uint32_t)mt * 2048;
                LDS32(af[mt][0], base + u0);
                LDS32(af[mt][1], base + 1024 + u0);
                LDS32(af[mt][2], base + u1);
                LDS32(af[mt][3], base + 1024 + u1);
            }
#pragma unroll
            for (int nt = 0; nt < 8; ++nt) {
                uint32_t b0, b1;
                uint32_t base = Bb + boff0 + (uint32_t)nt * 1024;
                LDS32(b0, base + u0);
                LDS32(b1, base + u1);
#pragma unroll
                for (int mt = 0; mt < 4; ++mt)
                    mma_tf32(acc[mt][nt][0], acc[mt][nt][1], acc[mt][nt][2], acc[mt][nt][3],
                             af[mt][0], af[mt][1], af[mt][2], af[mt][3], b0, b1);
            }
        }
    }

    // ---------------- epilogue
#pragma unroll
    for (int mt = 0; mt < 4; ++mt) {
#pragma unroll
        for (int nt = 0; nt < 8; ++nt) {
            int gm = m0 + wm + mt * 16 + g;
            int gn = n0 + wn + nt * 8 + tg * 2;
            float2 v0 = make_float2(acc[mt][nt][0], acc[mt][nt][1]);
            float2 v1 = make_float2(acc[mt][nt][2], acc[mt][nt][3]);
            *(float2*)&g_fm[(size_t)gm * C_INR + gn]       = v0;
            *(float2*)&g_fm[(size_t)(gm + 8) * C_INR + gn] = v1;
        }
    }
}

// ---------------------------------------------------------------------------
// ROI align: 2 blocks per ROI (64 channel-groups each)
// ---------------------------------------------------------------------------
__global__ __launch_bounds__(64)
void roi_kernel(const float* __restrict__ boxes)
{
    const int r     = blockIdx.x >> 1;
    const int c4    = ((blockIdx.x & 1) << 6) + threadIdx.x;
    const int frame = r >> 2;

    const float* bx = boxes + r * 4;
    float cx = bx[0], cy = bx[1], w = bx[2], h = bx[3];

    float x1 = ((cx - w * 0.5f) * 224.0f) * 0.0625f;
    float y1 = ((cy - h * 0.5f) * 224.0f) * 0.0625f;
    float x2 = ((cx + w * 0.5f) * 224.0f) * 0.0625f;
    float y2 = ((cy + h * 0.5f) * 224.0f) * 0.0625f;

    float roi_w = fmaxf(x2 - x1, 1.0f);
    float roi_h = fmaxf(y2 - y1, 1.0f);
    float bw = roi_w * (1.0f / 3.0f);
    float bh = roi_h * (1.0f / 3.0f);

    float4 acc[9];
#pragma unroll
    for (int i = 0; i < 9; i++) acc[i] = make_float4(0.f, 0.f, 0.f, 0.f);

    const float* fmf = g_fm + (size_t)frame * HWP * C_INR + c4 * 4;

#pragma unroll
    for (int iy = 0; iy < 6; iy++) {
        float yy = y1 + (float)(iy >> 1) * bh + ((float)(iy & 1) + 0.5f) * bh * 0.5f;
        bool vy = (yy > -1.0f) && (yy < 14.0f);
        float yc = fminf(fmaxf(yy, 0.0f), 13.0f);
        int   yi0 = (int)floorf(yc);
        int   yi1 = min(yi0 + 1, 13);
        float ly = yc - (float)yi0;
        float hy = 1.0f - ly;

#pragma unroll
        for (int ix = 0; ix < 6; ix++) {
            float xx = x1 + (float)(ix >> 1) * bw + ((float)(ix & 1) + 0.5f) * bw * 0.5f;
            bool v = vy && (xx > -1.0f) && (xx < 14.0f);
            if (!v) continue;
            float xc = fminf(fmaxf(xx, 0.0f), 13.0f);
            int   xi0 = (int)floorf(xc);
            int   xi1 = min(xi0 + 1, 13);
            float lx = xc - (float)xi0;
            float hx = 1.0f - lx;

            float w00 = hy * hx, w01 = hy * lx, w10 = ly * hx, w11 = ly * lx;

            float4 p00 = *(const float4*)(fmf + (yi0 * WW + xi0) * C_INR);
            float4 p01 = *(const float4*)(fmf + (yi0 * WW + xi1) * C_INR);
            float4 p10 = *(const float4*)(fmf + (yi1 * WW + xi0) * C_INR);
            float4 p11 = *(const float4*)(fmf + (yi1 * WW + xi1) * C_INR);

            int bin = (iy >> 1) * 3 + (ix >> 1);
            acc[bin].x += w00 * p00.x + w01 * p01.x + w10 * p10.x + w11 * p11.x;
            acc[bin].y += w00 * p00.y + w01 * p01.y + w10 * p10.y + w11 * p11.y;
            acc[bin].z += w00 * p00.z + w01 * p01.z + w10 * p10.z + w11 * p11.z;
            acc[bin].w += w00 * p00.w + w01 * p01.w + w10 * p10.w + w11 * p11.w;
        }
    }

    float tmp[36];
#pragma unroll
    for (int bin = 0; bin < 9; bin++) {
        tmp[0 * 9 + bin] = __uint_as_float(f2tf32(acc[bin].x * 0.25f));
        tmp[1 * 9 + bin] = __uint_as_float(f2tf32(acc[bin].y * 0.25f));
        tmp[2 * 9 + bin] = __uint_as_float(f2tf32(acc[bin].z * 0.25f));
        tmp[3 * 9 + bin] = __uint_as_float(f2tf32(acc[bin].w * 0.25f));
    }
    float* out = g_feats + (size_t)r * K_FEATS + c4 * 36;
#pragma unroll
    for (int q = 0; q < 9; q++)
        *(float4*)(out + q * 4) = *(float4*)&tmp[q * 4];
}

// ---------------------------------------------------------------------------
__global__ void zero_kernel()
{
    int i = blockIdx.x * blockDim.x + threadIdx.x;
    if (i < NROIS * C_INR) g_regacc[i] = 0.0f;
}

// ---------------------------------------------------------------------------
// GEMM2 via mma.sync tf32, split-K=8
// ---------------------------------------------------------------------------
#define G2_SPLITS 8
#define G2_KC     (K_FEATS / G2_SPLITS)   // 576
#define G2_ITERS  (G2_KC / 32)            // 18
#define G2_SMEM   65536

__global__ void __launch_bounds__(256, 2) gemm2_mma()
{
    extern __shared__ char sm[];
    const uint32_t sbase = smem_u32(sm);
    const int tid  = threadIdx.x;
    const int wid  = tid >> 5;
    const int lane = tid & 31;
    const int m0   = blockIdx.x * 128;
    const int n0   = blockIdx.y * 128;
    const int kb   = blockIdx.z * G2_KC;

    const int wm = (wid >> 2) * 64;
    const int wn = (wid & 3) * 32;
    const int g  = lane >> 2;
    const int tg = lane & 3;
    const uint32_t frag_sw = ((uint32_t)g & 7) << 4;
    const uint32_t aoff0 = (uint32_t)(wm + g) * 128;
    const uint32_t boff0 = (uint32_t)(wn + g) * 128 + 32768u;

    float acc[4][4][4];
#pragma unroll
    for (int i = 0; i < 4; i++)
#pragma unroll
        for (int j = 0; j < 4; j++)
#pragma unroll
            for (int r = 0; r < 4; r++) acc[i][j][r] = 0.0f;

#pragma unroll
    for (int i = 0; i < 4; ++i) {
        int idx = tid + i * 256;
        int rr = idx >> 3, c = idx & 7;
        uint32_t sw = (((uint32_t)c * 16) ^ (((uint32_t)rr & 7) << 4));
        const float* asrc = g_feats + (size_t)(m0 + rr) * K_FEATS + kb + c * 4;
        const float* bsrc = g_rewt  + (size_t)(n0 + rr) * K_FEATS + kb + c * 4;
        uint32_t adst = sbase + (uint32_t)rr * 128 + sw;
        uint32_t bdst = sbase + 32768u + (uint32_t)rr * 128 + sw;
        asm volatile("cp.async.cg.shared.global [%0], [%1], 16;" :: "r"(adst), "l"(asrc));
        asm volatile("cp.async.cg.shared.global [%0], [%1], 16;" :: "r"(bdst), "l"(bsrc));
    }
    asm volatile("cp.async.commit_group;" ::: "memory");

    for (int s = 0; s < G2_ITERS; ++s) {
        const uint32_t bufo = (s & 1) ? 16384u : 0u;

        asm volatile("cp.async.wait_group 0;" ::: "memory");
        __syncthreads();

        if (s + 1 < G2_ITERS) {
            const int k0n = kb + (s + 1) * 32;
            const uint32_t nb = (s + 1) & 1 ? 16384u : 0u;
#pragma unroll
            for (int i = 0; i < 4; ++i) {
                int idx = tid + i * 256;
                int rr = idx >> 3, c = idx & 7;
                uint32_t sw = (((uint32_t)c * 16) ^ (((uint32_t)rr & 7) << 4));
                const float* asrc = g_feats + (size_t)(m0 + rr) * K_FEATS + k0n + c * 4;
                const float* bsrc = g_rewt  + (size_t)(n0 + rr) * K_FEATS + k0n + c * 4;
                uint32_t adst = sbase + nb + (uint32_t)rr * 128 + sw;
                uint32_t bdst = sbase + 32768u + nb + (uint32_t)rr * 128 + sw;
                asm volatile("cp.async.cg.shared.global [%0], [%1], 16;" :: "r"(adst), "l"(asrc));
                asm volatile("cp.async.cg.shared.global [%0], [%1], 16;" :: "r"(bdst), "l"(bsrc));
            }
            asm volatile("cp.async.commit_group;" ::: "memory");
        }

        const uint32_t Ab = sbase + bufo;
        const uint32_t Bb = sbase + bufo;
#pragma unroll
        for (int kc = 0; kc < 4; ++kc) {
            const uint32_t u0 = (uint32_t)(kc * 32 + tg * 4)      ^ frag_sw;
            const uint32_t u1 = (uint32_t)(kc * 32 + tg * 4 + 16) ^ frag_sw;

            uint32_t af[4][4];
#pragma unroll
            for (int mt = 0; mt < 4; ++mt) {
                uint32_t base = Ab + aoff0 + (uint32_t)mt * 2048;
                LDS32(af[mt][0], base + u0);
                LDS32(af[mt][1], base + 1024 + u0);
                LDS32(af[mt][2], base + u1);
                LDS32(af[mt][3], base + 1024 + u1);
            }
#pragma unroll
            for (int nt = 0; nt < 4; ++nt) {
                uint32_t b0, b1;
                uint32_t base = Bb + boff0 + (uint32_t)nt * 1024;
                LDS32(b0, base + u0);
                LDS32(b1, base + u1);
#pragma unroll
                for (int mt = 0; mt < 4; ++mt)
                    mma_tf32(acc[mt][nt][0], acc[mt][nt][1], acc[mt][nt][2], acc[mt][nt][3],
                             af[mt][0], af[mt][1], af[mt][2], af[mt][3], b0, b1);
            }
        }
    }

#pragma unroll
    for (int mt = 0; mt < 4; ++mt) {
#pragma unroll
        for (int nt = 0; nt < 4; ++nt) {
            int gm = m0 + wm + mt * 16 + g;
            int gn = n0 + wn + nt * 8 + tg * 2;
            atomicAdd(&g_regacc[(size_t)gm * C_INR + gn],           acc[mt][nt][0]);
            atomicAdd(&g_regacc[(size_t)gm * C_INR + gn + 1],       acc[mt][nt][1]);
            atomicAdd(&g_regacc[(size_t)(gm + 8) * C_INR + gn],     acc[mt][nt][2]);
            atomicAdd(&g_regacc[(size_t)(gm + 8) * C_INR + gn + 1], acc[mt][nt][3]);
        }
    }
}

// ---------------------------------------------------------------------------
__global__ __launch_bounds__(512)
void reduce_kernel(const float* __restrict__ re_b, const int* __restrict__ cat,
                   float* __restrict__ out, int out_size)
{
    const int b = blockIdx.x;
    const int j = threadIdx.x;
    const float bias = re_b[j];

    float rm[NB];
    float p = 0.0f;
#pragma unroll
    for (int nb = 0; nb < NB; nb++) {
        float s = 0.0f;
#pragma unroll
        for (int t = 0; t < TT; t++) {
            int r = (b * TT + t) * NB + nb;
            s += fmaxf(g_regacc[(size_t)r * C_INR + j] + bias, 0.0f);
        }
        rm[nb] = s * 0.125f;
        p += rm[nb];
    }
    g_pooled[b * C_INR + j] = p * 0.25f;

    int c2 = cat[b * NB + 2];
    int c3 = cat[b * NB + 3];
    int o0 = (c2 == 0 && c3 != 0) ? 1 : 0;
    int o1 = 1 - o0;
    g_objfeas[(2 * b) * C_INR + j]     = rm[2 + o0];
    g_objfeas[(2 * b + 1) * C_INR + j] = rm[2 + o1];

    if (j == 0 && out_size >= OUT_LABEL_OFF + 2 * BB) {
        out[OUT_LABEL_OFF + 2 * b]     = (float)(o0 == 0 ? c2 : c3);
        out[OUT_LABEL_OFF + 2 * b + 1] = (float)(o1 == 0 ? c2 : c3);
    }
}

// ---------------------------------------------------------------------------
// Fused two-layer head
// ---------------------------------------------------------------------------
__global__ __launch_bounds__(256)
void head2_kernel(const float* __restrict__ X,
                  const float* __restrict__ W1, const float* __restrict__ b1,
                  const float* __restrict__ W2, const float* __restrict__ b2,
                  float* __restrict__ out, int N2)
{
    __shared__ float xs[512];
    __shared__ float hid[512];
    const int m = blockIdx.x;
    for (int k = threadIdx.x; k < 512; k += 256) xs[k] = X[m * 512 + k];
    __syncthreads();

#pragma unroll
    for (int rr = 0; rr < 2; ++rr) {
        int n = threadIdx.x + rr * 256;
        float a = b1[n];
#pragma unroll 8
        for (int k = 0; k < 512; ++k)
            a = fmaf(xs[k], __ldg(&W1[(size_t)k * 512 + n]), a);
        hid[n] = a;
    }
    __syncthreads();

    for (int n = threadIdx.x; n < N2; n += 256) {
        float a = b2[n];
#pragma unroll 8
        for (int k = 0; k < 512; ++k)
            a = fmaf(hid[k], __ldg(&W2[(size_t)k * N2 + n]), a);
        out[m * N2 + n] = a;
    }
}

// ---------------------------------------------------------------------------
// kernel_launch
// ---------------------------------------------------------------------------
extern "C" void kernel_launch(void* const* d_in, const int* in_sizes, int n_in,
                              void* d_out, int out_size)
{
    const float* x       = (const float*)d_in[0];
    const float* boxes   = (const float*)d_in[1];
    const int*   cat     = (const int*)  d_in[2];
    const float* conv5_w = (const float*)d_in[3];
    const float* re_w    = (const float*)d_in[4];
    const float* re_b    = (const float*)d_in[5];
    const float* oc1_w   = (const float*)d_in[6];
    const float* oc1_b   = (const float*)d_in[7];
    const float* oc2_w   = (const float*)d_in[8];
    const float* oc2_b   = (const float*)d_in[9];
    const float* pr1_w   = (const float*)d_in[10];
    const float* pr1_b   = (const float*)d_in[11];
    const float* pr2_w   = (const float*)d_in[12];
    const float* pr2_b   = (const float*)d_in[13];
    float* out = (float*)d_out;

    float *p_pooled, *p_objfeas;
    cudaGetSymbolAddress((void**)&p_pooled,  g_pooled);
    cudaGetSymbolAddress((void**)&p_objfeas, g_objfeas);

    cudaFuncSetAttribute(gemm1_mma, cudaFuncAttributeMaxDynamicSharedMemorySize, G1_SMEM);
    cudaFuncSetAttribute(gemm2_mma, cudaFuncAttributeMaxDynamicSharedMemorySize, G2_SMEM);

    // 0) pre-passes: w round, x transpose+round, re_w transpose, zero
    wconv_kernel<<<(C_INR * C_INC + 511) / 512, 512>>>(conv5_w);
    xt_kernel<<<dim3(C_INC / 32, MLOC / 32, BB), dim3(32, 8)>>>(x);
    rewt_kernel<<<dim3(K_FEATS / 32, C_INR / 32), dim3(32, 8)>>>(re_w);
    zero_kernel<<<(NROIS * C_INR + 255) / 256, 256>>>();

    // 1) big 1x1-conv GEMM (tf32 mma, 64x64 warp tiles, cp.async both, 3 CTAs/SM)
    gemm1_mma<<<dim3(C_INR / 128, M_TOTAL / 128), 128, G1_SMEM>>>();

    // 2) ROI align (2 blocks/ROI)
    roi_kernel<<<NROIS * 2, 64>>>(boxes);

    // 3) feats @ re_w, split-K=8 + atomics
    gemm2_mma<<<dim3(4, 4, G2_SPLITS), 256, G2_SMEM>>>();

    // 4) bias+relu+T-mean, NB-mean pool, obj selection + labels
    reduce_kernel<<<BB, 512>>>(re_b, cat, out, out_size);

    // 5) fused heads
    head2_kernel<<<2 * BB, 256>>>(p_objfeas, oc1_w, oc1_b, oc2_w, oc2_b,
                                  out + OUT_OBJCLS_OFF, NOBJ);
    head2_kernel<<<BB, 256>>>(p_pooled, pr1_w, pr1_b, pr2_w, pr2_b, out, NCLS);
}

// round 11
// speedup vs baseline: 2.3221x; 1.5381x over previous
#include <cuda_runtime.h>
#include <cuda_bf16.h>
#include <math.h>
#include <stdint.h>

// ---------------------------------------------------------------------------
// Problem constants
// ---------------------------------------------------------------------------
#define BB        16
#define TT        8
#define NB        4
#define C_INC     2048       // C_IN
#define C_INR     512        // C_INNER
#define WW        14
#define HWP       196        // H*W
#define MLOC      1568       // T*H*W per batch
#define M_TOTAL   25088
#define K_FEATS   4608       // C_INNER*9
#define NROIS     512
#define NBINS     9
#define M_ROIX    4608       // NROIS*NBINS
#define NCLS      174
#define NOBJ      301

#define OUT_OBJCLS_OFF 2784
#define OUT_LABEL_OFF  12416

// ---------------------------------------------------------------------------
// Scratch
// ---------------------------------------------------------------------------
__device__ float g_xt[M_TOTAL * C_INC];        // x^T tf32(RN), [m][k]
__device__ float g_roix[M_ROIX * C_INC];       // pooled x, [(roi,bin)][k], tf32
__device__ float g_wtf[C_INR * C_INC];         // conv5_w tf32(RN), [n][k]
__device__ float g_rewt[C_INR * K_FEATS];      // re_w^T tf32, [n][r], r=c*9+bin
__device__ float g_rewt2[C_INR * K_FEATS];     // re_w^T tf32, [n][kp], kp=bin*512+c
__device__ float g_feats[NROIS * K_FEATS];     // [roi][kp=bin*512+c], tf32
__device__ float g_regacc[NROIS * C_INR];
__device__ float g_pooled[BB * C_INR];
__device__ float g_objfeas[2 * BB * C_INR];

// ---------------------------------------------------------------------------
// Helpers
// ---------------------------------------------------------------------------
__device__ __forceinline__ uint32_t smem_u32(const void* p) {
    uint32_t a;
    asm("{ .reg .u64 t; cvta.to.shared.u64 t, %1; cvt.u32.u64 %0, t; }"
        : "=r"(a) : "l"(p));
    return a;
}
__device__ __forceinline__ uint32_t f2tf32(float v) {
    uint32_t o;
    asm("cvt.rna.tf32.f32 %0, %1;" : "=r"(o) : "f"(v));
    return o;
}
#define LDS32(v, a) asm volatile("ld.shared.b32 %0, [%1];" : "=r"(v) : "r"(a))
#define CP_ASYNC16(dst, src) \
    asm volatile("cp.async.cg.shared.global [%0], [%1], 16;" :: "r"(dst), "l"(src))
#define CP_COMMIT() asm volatile("cp.async.commit_group;" ::: "memory")
#define CP_WAIT1()  asm volatile("cp.async.wait_group 1;" ::: "memory")

__device__ __forceinline__ void mma_tf32(float& d0, float& d1, float& d2, float& d3,
                                         uint32_t a0, uint32_t a1, uint32_t a2, uint32_t a3,
                                         uint32_t b0, uint32_t b1)
{
    asm volatile(
        "mma.sync.aligned.m16n8k8.row.col.f32.tf32.tf32.f32 "
        "{%0,%1,%2,%3}, {%4,%5,%6,%7}, {%8,%9}, {%0,%1,%2,%3};"
        : "+f"(d0), "+f"(d1), "+f"(d2), "+f"(d3)
        : "r"(a0), "r"(a1), "r"(a2), "r"(a3), "r"(b0), "r"(b1));
}

// Stage loader shared by both GEMMs: 4 rows x 16B per thread per tile, both
// A and B tiles of one 128x32 k-chunk into stage st (16KB apart, B at +49152).
__device__ __forceinline__ void load_stage_pair(
    uint32_t sbase, int st, const float* __restrict__ Asrc,
    const float* __restrict__ Bsrc, size_t ldk, int m0, int n0, int k0,
    int lrr, int lcc)
{
    const uint32_t so = (uint32_t)st * 16384u;
#pragma unroll
    for (int i = 0; i < 4; ++i) {
        int rr = lrr + i * 32;
        uint32_t sw = (((uint32_t)lcc * 16) ^ (((uint32_t)rr & 7) << 4));
        const float* asrc = Asrc + (size_t)(m0 + rr) * ldk + k0 + lcc * 4;
        const float* bsrc = Bsrc + (size_t)(n0 + rr) * ldk + k0 + lcc * 4;
        CP_ASYNC16(sbase + so + (uint32_t)rr * 128 + sw, asrc);
        CP_ASYNC16(sbase + 49152u + so + (uint32_t)rr * 128 + sw, bsrc);
    }
}

// ---------------------------------------------------------------------------
// Pre-passes
// ---------------------------------------------------------------------------
__global__ void wconv_kernel(const float* __restrict__ w)
{
    int i = blockIdx.x * blockDim.x + threadIdx.x;
    if (i < C_INR * C_INC)
        g_wtf[i] = __uint_as_float(f2tf32(w[i]));
}

// x[b][k][t*hw] -> g_xt[(b,t,hw)][k], tf32(RN). Tiled 32x32.
__global__ void xt_kernel(const float* __restrict__ x)
{
    __shared__ float t[32][33];
    const int k0  = blockIdx.x * 32;
    const int ml0 = blockIdx.y * 32;
    const int b   = blockIdx.z;
    const int cx  = threadIdx.x;
    const int ty  = threadIdx.y;

    const float* src = x + (size_t)b * C_INC * MLOC + (size_t)k0 * MLOC + ml0;
#pragma unroll
    for (int j = 0; j < 4; ++j) {
        int ry = ty + j * 8;
        t[ry][cx] = src[(size_t)ry * MLOC + cx];
    }
    __syncthreads();
    float* dst = g_xt + (size_t)(b * MLOC + ml0) * C_INC + k0;
#pragma unroll
    for (int j = 0; j < 4; ++j) {
        int ry = ty + j * 8;
        dst[(size_t)ry * C_INC + cx] = __uint_as_float(f2tf32(t[cx][ry]));
    }
}

// re_w^T natural order: g_rewt[n][r] = tf32(re_w[r][n])
__global__ void rewt_kernel(const float* __restrict__ rw)
{
    __shared__ float t[32][33];
    const int r0 = blockIdx.x * 32;
    const int c0 = blockIdx.y * 32;
    const int cx = threadIdx.x;
    const int ty = threadIdx.y;
#pragma unroll
    for (int j = 0; j < 4; ++j) {
        int ry = ty + j * 8;
        t[ry][cx] = rw[(size_t)(r0 + ry) * C_INR + c0 + cx];
    }
    __syncthreads();
#pragma unroll
    for (int j = 0; j < 4; ++j) {
        int ry = ty + j * 8;
        g_rewt[(size_t)(c0 + ry) * K_FEATS + r0 + cx] =
            __uint_as_float(f2tf32(t[cx][ry]));
    }
}

// Column permute: g_rewt2[n][kp=bin*512+c] = g_rewt[n][r=c*9+bin]
__global__ __launch_bounds__(512) void rewt2_kernel()
{
    __shared__ float s[K_FEATS];
    const int n = blockIdx.x;
    const int tid = threadIdx.x;
#pragma unroll
    for (int i = 0; i < 9; ++i)
        s[tid + i * 512] = g_rewt[(size_t)n * K_FEATS + tid + i * 512];
    __syncthreads();
#pragma unroll
    for (int i = 0; i < 9; ++i) {
        int kp = tid + i * 512;                   // bin = i, c = tid
        g_rewt2[(size_t)n * K_FEATS + kp] = s[tid * 9 + i];
    }
}

__global__ void zero_kernel()
{
    int i = blockIdx.x * blockDim.x + threadIdx.x;
    if (i < NROIS * C_INR) g_regacc[i] = 0.0f;
}

// ---------------------------------------------------------------------------
// ROI bilinear pooling on xt (linear in channels; commuted before the conv).
// One block per ROI, 512 threads = one float4 channel-group each.
// ---------------------------------------------------------------------------
__global__ __launch_bounds__(512)
void roix_kernel(const float* __restrict__ boxes)
{
    const int r     = blockIdx.x;
    const int frame = r >> 2;
    const int tid   = threadIdx.x;

    const float* bx = boxes + r * 4;
    float cx = bx[0], cy = bx[1], w = bx[2], h = bx[3];

    float x1 = ((cx - w * 0.5f) * 224.0f) * 0.0625f;
    float y1 = ((cy - h * 0.5f) * 224.0f) * 0.0625f;
    float x2 = ((cx + w * 0.5f) * 224.0f) * 0.0625f;
    float y2 = ((cy + h * 0.5f) * 224.0f) * 0.0625f;

    float roi_w = fmaxf(x2 - x1, 1.0f);
    float roi_h = fmaxf(y2 - y1, 1.0f);
    float bw = roi_w * (1.0f / 3.0f);
    float bh = roi_h * (1.0f / 3.0f);

    float4 acc[9];
#pragma unroll
    for (int i = 0; i < 9; i++) acc[i] = make_float4(0.f, 0.f, 0.f, 0.f);

    const float* base = g_xt + (size_t)frame * HWP * C_INC + tid * 4;

#pragma unroll
    for (int iy = 0; iy < 6; iy++) {
        float yy = y1 + (float)(iy >> 1) * bh + ((float)(iy & 1) + 0.5f) * bh * 0.5f;
        bool vy = (yy > -1.0f) && (yy < 14.0f);
        float yc = fminf(fmaxf(yy, 0.0f), 13.0f);
        int   yi0 = (int)floorf(yc);
        int   yi1 = min(yi0 + 1, 13);
        float ly = yc - (float)yi0;
        float hy = 1.0f - ly;

#pragma unroll
        for (int ix = 0; ix < 6; ix++) {
            float xx = x1 + (float)(ix >> 1) * bw + ((float)(ix & 1) + 0.5f) * bw * 0.5f;
            bool v = vy && (xx > -1.0f) && (xx < 14.0f);
            if (!v) continue;
            float xc = fminf(fmaxf(xx, 0.0f), 13.0f);
            int   xi0 = (int)floorf(xc);
            int   xi1 = min(xi0 + 1, 13);
            float lx = xc - (float)xi0;
            float hx = 1.0f - lx;

            float w00 = hy * hx, w01 = hy * lx, w10 = ly * hx, w11 = ly * lx;

            float4 p00 = *(const float4*)(base + (size_t)(yi0 * WW + xi0) * C_INC);
            float4 p01 = *(const float4*)(base + (size_t)(yi0 * WW + xi1) * C_INC);
            float4 p10 = *(const float4*)(base + (size_t)(yi1 * WW + xi0) * C_INC);
            float4 p11 = *(const float4*)(base + (size_t)(yi1 * WW + xi1) * C_INC);

            int bin = (iy >> 1) * 3 + (ix >> 1);
            acc[bin].x += w00 * p00.x + w01 * p01.x + w10 * p10.x + w11 * p11.x;
            acc[bin].y += w00 * p00.y + w01 * p01.y + w10 * p10.y + w11 * p11.y;
            acc[bin].z += w00 * p00.z + w01 * p01.z + w10 * p10.z + w11 * p11.z;
            acc[bin].w += w00 * p00.w + w01 * p01.w + w10 * p10.w + w11 * p11.w;
        }
    }

#pragma unroll
    for (int bin = 0; bin < 9; bin++) {
        float4 o;
        o.x = __uint_as_float(f2tf32(acc[bin].x * 0.25f));
        o.y = __uint_as_float(f2tf32(acc[bin].y * 0.25f));
        o.z = __uint_as_float(f2tf32(acc[bin].z * 0.25f));
        o.w = __uint_as_float(f2tf32(acc[bin].w * 0.25f));
        *(float4*)(g_roix + (size_t)(r * 9 + bin) * C_INC + tid * 4) = o;
    }
}

// ---------------------------------------------------------------------------
// GEMM1b: feats[roi][bin*512+n] = sum_k roix[(roi,bin)][k] * wtf[n][k]
//   M=4608, N=512, K=2048. CTA 128x128, BK=32, 8 warps (2x4), warp 64x32.
//   3-stage cp.async pipeline, wait_group 1.
// ---------------------------------------------------------------------------
#define G1B_ITERS  (C_INC / 32)     // 64
#define GP_SMEM    98304            // 3 stages x (16K A + 16K B)

__global__ void __launch_bounds__(256, 2) gemm1b_mma()
{
    extern __shared__ char sm[];
    const uint32_t sbase = smem_u32(sm);
    const int tid  = threadIdx.x;
    const int wid  = tid >> 5;
    const int lane = tid & 31;
    const int n0   = blockIdx.x * 128;
    const int m0   = blockIdx.y * 128;

    const int wm = (wid >> 2) * 64;
    const int wn = (wid & 3) * 32;
    const int g  = lane >> 2;
    const int tg = lane & 3;
    const uint32_t frag_sw = ((uint32_t)g & 7) << 4;
    const uint32_t aoff0 = (uint32_t)(wm + g) * 128;
    const uint32_t boff0 = (uint32_t)(wn + g) * 128 + 49152u;

    float acc[4][4][4];
#pragma unroll
    for (int i = 0; i < 4; i++)
#pragma unroll
        for (int j = 0; j < 4; j++)
#pragma unroll
            for (int r = 0; r < 4; r++) acc[i][j][r] = 0.0f;

    const int lrr = tid >> 3;
    const int lcc = tid & 7;

    load_stage_pair(sbase, 0, g_roix, g_wtf, C_INC, m0, n0, 0,  lrr, lcc); CP_COMMIT();
    load_stage_pair(sbase, 1, g_roix, g_wtf, C_INC, m0, n0, 32, lrr, lcc); CP_COMMIT();

    for (int s = 0; s < G1B_ITERS; ++s) {
        CP_WAIT1();
        __syncthreads();

        if (s + 2 < G1B_ITERS)
            load_stage_pair(sbase, (s + 2) % 3, g_roix, g_wtf, C_INC,
                            m0, n0, (s + 2) * 32, lrr, lcc);
        CP_COMMIT();   // empty group in the tail keeps wait_group 1 exact

        const uint32_t so = (uint32_t)(s % 3) * 16384u;
        const uint32_t Ab = sbase + so;
        const uint32_t Bb = sbase + so;    // boff0 carries +49152
#pragma unroll
        for (int kc = 0; kc < 4; ++kc) {
            const uint32_t u0 = (uint32_t)(kc * 32 + tg * 4)      ^ frag_sw;
            const uint32_t u1 = (uint32_t)(kc * 32 + tg * 4 + 16) ^ frag_sw;

            uint32_t af[4][4];
#pragma unroll
            for (int mt = 0; mt < 4; ++mt) {
                uint32_t base = Ab + aoff0 + (uint32_t)mt * 2048;
                LDS32(af[mt][0], base + u0);
                LDS32(af[mt][1], base + 1024 + u0);
                LDS32(af[mt][2], base + u1);
                LDS32(af[mt][3], base + 1024 + u1);
            }
#pragma unroll
            for (int nt = 0; nt < 4; ++nt) {
                uint32_t b0, b1;
                uint32_t base = Bb + boff0 + (uint32_t)nt * 1024;
                LDS32(b0, base + u0);
                LDS32(b1, base + u1);
#pragma unroll
                for (int mt = 0; mt < 4; ++mt)
                    mma_tf32(acc[mt][nt][0], acc[mt][nt][1], acc[mt][nt][2], acc[mt][nt][3],
                             af[mt][0], af[mt][1], af[mt][2], af[mt][3], b0, b1);
            }
        }
        __syncthreads();
    }

    // epilogue: feats[roi][bin*512 + n], tf32-rounded
#pragma unroll
    for (int mt = 0; mt < 4; ++mt) {
#pragma unroll
        for (int nt = 0; nt < 4; ++nt) {
#pragma unroll
            for (int half = 0; half < 2; ++half) {
                int gm = m0 + wm + mt * 16 + g + half * 8;
                int gn = n0 + wn + nt * 8 + tg * 2;
                int roi = gm / 9;
                int bin = gm - roi * 9;
                float* dst = g_feats + (size_t)roi * K_FEATS + bin * 512 + gn;
                float2 v;
                v.x = __uint_as_float(f2tf32(acc[mt][nt][half * 2 + 0]));
                v.y = __uint_as_float(f2tf32(acc[mt][nt][half * 2 + 1]));
                *(float2*)dst = v;
            }
        }
    }
}

// ---------------------------------------------------------------------------
// GEMM2: regacc[roi][n] += feats[roi][kp] * rewt2[n][kp]. Split-K=8,
// 3-stage pipeline, atomicAdd epilogue.
// ---------------------------------------------------------------------------
#define G2_SPLITS 8
#define G2_KC     (K_FEATS / G2_SPLITS)   // 576
#define G2_ITERS  (G2_KC / 32)            // 18

__global__ void __launch_bounds__(256, 2) gemm2_mma()
{
    extern __shared__ char sm[];
    const uint32_t sbase = smem_u32(sm);
    const int tid  = threadIdx.x;
    const int wid  = tid >> 5;
    const int lane = tid & 31;
    const int m0   = blockIdx.x * 128;
    const int n0   = blockIdx.y * 128;
    const int kb   = blockIdx.z * G2_KC;

    const int wm = (wid >> 2) * 64;
    const int wn = (wid & 3) * 32;
    const int g  = lane >> 2;
    const int tg = lane & 3;
    const uint32_t frag_sw = ((uint32_t)g & 7) << 4;
    const uint32_t aoff0 = (uint32_t)(wm + g) * 128;
    const uint32_t boff0 = (uint32_t)(wn + g) * 128 + 49152u;

    float acc[4][4][4];
#pragma unroll
    for (int i = 0; i < 4; i++)
#pragma unroll
        for (int j = 0; j < 4; j++)
#pragma unroll
            for (int r = 0; r < 4; r++) acc[i][j][r] = 0.0f;

    const int lrr = tid >> 3;
    const int lcc = tid & 7;

    load_stage_pair(sbase, 0, g_feats, g_rewt2, K_FEATS, m0, n0, kb,      lrr, lcc); CP_COMMIT();
    load_stage_pair(sbase, 1, g_feats, g_rewt2, K_FEATS, m0, n0, kb + 32, lrr, lcc); CP_COMMIT();

    for (int s = 0; s < G2_ITERS; ++s) {
        CP_WAIT1();
        __syncthreads();

        if (s + 2 < G2_ITERS)
            load_stage_pair(sbase, (s + 2) % 3, g_feats, g_rewt2, K_FEATS,
                            m0, n0, kb + (s + 2) * 32, lrr, lcc);
        CP_COMMIT();

        const uint32_t so = (uint32_t)(s % 3) * 16384u;
        const uint32_t Ab = sbase + so;
        const uint32_t Bb = sbase + so;
#pragma unroll
        for (int kc = 0; kc < 4; ++kc) {
            const uint32_t u0 = (uint32_t)(kc * 32 + tg * 4)      ^ frag_sw;
            const uint32_t u1 = (uint32_t)(kc * 32 + tg * 4 + 16) ^ frag_sw;

            uint32_t af[4][4];
#pragma unroll
            for (int mt = 0; mt < 4; ++mt) {
                uint32_t base = Ab + aoff0 + (uint32_t)mt * 2048;
                LDS32(af[mt][0], base + u0);
                LDS32(af[mt][1], base + 1024 + u0);
                LDS32(af[mt][2], base + u1);
                LDS32(af[mt][3], base + 1024 + u1);
            }
#pragma unroll
            for (int nt = 0; nt < 4; ++nt) {
                uint32_t b0, b1;
                uint32_t base = Bb + boff0 + (uint32_t)nt * 1024;
                LDS32(b0, base + u0);
                LDS32(b1, base + u1);
#pragma unroll
                for (int mt = 0; mt < 4; ++mt)
                    mma_tf32(acc[mt][nt][0], acc[mt][nt][1], acc[mt][nt][2], acc[mt][nt][3],
                             af[mt][0], af[mt][1], af[mt][2], af[mt][3], b0, b1);
            }
        }
        __syncthreads();
    }

#pragma unroll
    for (int mt = 0; mt < 4; ++mt) {
#pragma unroll
        for (int nt = 0; nt < 4; ++nt) {
            int gm = m0 + wm + mt * 16 + g;
            int gn = n0 + wn + nt * 8 + tg * 2;
            atomicAdd(&g_regacc[(size_t)gm * C_INR + gn],           acc[mt][nt][0]);
            atomicAdd(&g_regacc[(size_t)gm * C_INR + gn + 1],       acc[mt][nt][1]);
            atomicAdd(&g_regacc[(size_t)(gm + 8) * C_INR + gn],     acc[mt][nt][2]);
            atomicAdd(&g_regacc[(size_t)(gm + 8) * C_INR + gn + 1], acc[mt][nt][3]);
        }
    }
}

// ---------------------------------------------------------------------------
__global__ __launch_bounds__(512)
void reduce_kernel(const float* __restrict__ re_b, const int* __restrict__ cat,
                   float* __restrict__ out, int out_size)
{
    const int b = blockIdx.x;
    const int j = threadIdx.x;
    const float bias = re_b[j];

    float rm[NB];
    float p = 0.0f;
#pragma unroll
    for (int nb = 0; nb < NB; nb++) {
        float s = 0.0f;
#pragma unroll
        for (int t = 0; t < TT; t++) {
            int r = (b * TT + t) * NB + nb;
            s += fmaxf(g_regacc[(size_t)r * C_INR + j] + bias, 0.0f);
        }
        rm[nb] = s * 0.125f;
        p += rm[nb];
    }
    g_pooled[b * C_INR + j] = p * 0.25f;

    int c2 = cat[b * NB + 2];
    int c3 = cat[b * NB + 3];
    int o0 = (c2 == 0 && c3 != 0) ? 1 : 0;
    int o1 = 1 - o0;
    g_objfeas[(2 * b) * C_INR + j]     = rm[2 + o0];
    g_objfeas[(2 * b + 1) * C_INR + j] = rm[2 + o1];

    if (j == 0 && out_size >= OUT_LABEL_OFF + 2 * BB) {
        out[OUT_LABEL_OFF + 2 * b]     = (float)(o0 == 0 ? c2 : c3);
        out[OUT_LABEL_OFF + 2 * b + 1] = (float)(o1 == 0 ? c2 : c3);
    }
}

// ---------------------------------------------------------------------------
// Fused two-layer head
// ---------------------------------------------------------------------------
__global__ __launch_bounds__(256)
void head2_kernel(const float* __restrict__ X,
                  const float* __restrict__ W1, const float* __restrict__ b1,
                  const float* __restrict__ W2, const float* __restrict__ b2,
                  float* __restrict__ out, int N2)
{
    __shared__ float xs[512];
    __shared__ float hid[512];
    const int m = blockIdx.x;
    for (int k = threadIdx.x; k < 512; k += 256) xs[k] = X[m * 512 + k];
    __syncthreads();

#pragma unroll
    for (int rr = 0; rr < 2; ++rr) {
        int n = threadIdx.x + rr * 256;
        float a = b1[n];
#pragma unroll 8
        for (int k = 0; k < 512; ++k)
            a = fmaf(xs[k], __ldg(&W1[(size_t)k * 512 + n]), a);
        hid[n] = a;
    }
    __syncthreads();

    for (int n = threadIdx.x; n < N2; n += 256) {
        float a = b2[n];
#pragma unroll 8
        for (int k = 0; k < 512; ++k)
            a = fmaf(hid[k], __ldg(&W2[(size_t)k * N2 + n]), a);
        out[m * N2 + n] = a;
    }
}

// ---------------------------------------------------------------------------
// kernel_launch
// ---------------------------------------------------------------------------
extern "C" void kernel_launch(void* const* d_in, const int* in_sizes, int n_in,
                              void* d_out, int out_size)
{
    const float* x       = (const float*)d_in[0];
    const float* boxes   = (const float*)d_in[1];
    const int*   cat     = (const int*)  d_in[2];
    const float* conv5_w = (const float*)d_in[3];
    const float* re_w    = (const float*)d_in[4];
    const float* re_b    = (const float*)d_in[5];
    const float* oc1_w   = (const float*)d_in[6];
    const float* oc1_b   = (const float*)d_in[7];
    const float* oc2_w   = (const float*)d_in[8];
    const float* oc2_b   = (const float*)d_in[9];
    const float* pr1_w   = (const float*)d_in[10];
    const float* pr1_b   = (const float*)d_in[11];
    const float* pr2_w   = (const float*)d_in[12];
    const float* pr2_b   = (const float*)d_in[13];
    float* out = (float*)d_out;

    float *p_pooled, *p_objfeas;
    cudaGetSymbolAddress((void**)&p_pooled,  g_pooled);
    cudaGetSymbolAddress((void**)&p_objfeas, g_objfeas);

    cudaFuncSetAttribute(gemm1b_mma, cudaFuncAttributeMaxDynamicSharedMemorySize, GP_SMEM);
    cudaFuncSetAttribute(gemm2_mma,  cudaFuncAttributeMaxDynamicSharedMemorySize, GP_SMEM);

    // 0) pre-passes
    wconv_kernel<<<(C_INR * C_INC + 511) / 512, 512>>>(conv5_w);
    xt_kernel<<<dim3(C_INC / 32, MLOC / 32, BB), dim3(32, 8)>>>(x);
    rewt_kernel<<<dim3(K_FEATS / 32, C_INR / 32), dim3(32, 8)>>>(re_w);
    rewt2_kernel<<<C_INR, 512>>>();
    zero_kernel<<<(NROIS * C_INR + 255) / 256, 256>>>();

    // 1) ROI bilinear pooling on x (commuted before the 1x1 conv)
    roix_kernel<<<NROIS, 512>>>(boxes);

    // 2) small conv GEMM: roix @ conv5_w  (9.7 GFLOP instead of 52.6)
    gemm1b_mma<<<dim3(C_INR / 128, M_ROIX / 128), 256, GP_SMEM>>>();

    // 3) feats @ re_w, split-K=8 + atomics
    gemm2_mma<<<dim3(4, 4, G2_SPLITS), 256, GP_SMEM>>>();

    // 4) bias+relu+T-mean, NB-mean pool, obj selection + labels
    reduce_kernel<<<BB, 512>>>(re_b, cat, out, out_size);

    // 5) fused heads
    head2_kernel<<<2 * BB, 256>>>(p_objfeas, oc1_w, oc1_b, oc2_w, oc2_b,
                                  out + OUT_OBJCLS_OFF, NOBJ);
    head2_kernel<<<BB, 256>>>(p_pooled, pr1_w, pr1_b, pr2_w, pr2_b, out, NCLS);
}